// round 2
// baseline (speedup 1.0000x reference)
#include <cuda_runtime.h>
#include <cuda_bf16.h>
#include <stdint.h>

// Int8SymmetricLinear: out[M,N] = (X[M,K] @ dequant(W)[N,K]^T) + bias
// Harness materializes the int8 weight tensor as int32 (its dtype universe is
// {float32, int32, bfloat16}), so W is read as const int* here.
// Dequant deferred: acc = sum_k x*float(w); out = scale[n]*acc + bias[n].
//
// Round 1: SIMT SGEMM baseline. BM=BN=128, BK=8, 256 threads, 8x8 microtile.

#define BM 128
#define BN 128
#define BK 8
#define TM 8
#define TN 8

__global__ __launch_bounds__(256, 2)
void int8lin_sgemm_kernel(const float* __restrict__ X,
                          const int*   __restrict__ W,
                          const float* __restrict__ Wscale,
                          const float* __restrict__ Bias,
                          float* __restrict__ Out,
                          int M, int N, int K)
{
    __shared__ float As[BK][BM];   // transposed A tile: As[k][m]
    __shared__ float Bs[BK][BN];   // transposed W tile (int value as float): Bs[k][n]

    const int tid = threadIdx.x;
    const int tx = tid & 15;    // n-direction (16 threads)
    const int ty = tid >> 4;    // m-direction (16 threads)

    const int bm = blockIdx.y * BM;
    const int bn = blockIdx.x * BN;

    // Global-load mapping: 256 threads cover 128 rows x 8 cols, 4 elems each.
    const int ld_row = tid >> 1;          // 0..127
    const int ld_col = (tid & 1) * 4;     // 0 or 4

    const float* Aptr = X + (size_t)(bm + ld_row) * K + ld_col;
    const int*   Bptr = W + (size_t)(bn + ld_row) * K + ld_col;

    float acc[TM][TN];
#pragma unroll
    for (int i = 0; i < TM; i++)
#pragma unroll
        for (int j = 0; j < TN; j++) acc[i][j] = 0.0f;

    for (int kt = 0; kt < K; kt += BK) {
        // ---- load A tile (float4), store transposed ----
        float4 av = *reinterpret_cast<const float4*>(Aptr);
        Aptr += BK;
        As[ld_col + 0][ld_row] = av.x;
        As[ld_col + 1][ld_row] = av.y;
        As[ld_col + 2][ld_row] = av.z;
        As[ld_col + 3][ld_row] = av.w;

        // ---- load W tile (int4 = 4x int32), convert to float, store transposed ----
        int4 bv = *reinterpret_cast<const int4*>(Bptr);
        Bptr += BK;
        Bs[ld_col + 0][ld_row] = (float)bv.x;
        Bs[ld_col + 1][ld_row] = (float)bv.y;
        Bs[ld_col + 2][ld_row] = (float)bv.z;
        Bs[ld_col + 3][ld_row] = (float)bv.w;

        __syncthreads();

#pragma unroll
        for (int k = 0; k < BK; k++) {
            float ra[TM], rb[TN];
            float4 a0 = *reinterpret_cast<const float4*>(&As[k][ty * TM]);
            float4 a1 = *reinterpret_cast<const float4*>(&As[k][ty * TM + 4]);
            float4 b0 = *reinterpret_cast<const float4*>(&Bs[k][tx * TN]);
            float4 b1 = *reinterpret_cast<const float4*>(&Bs[k][tx * TN + 4]);
            ra[0]=a0.x; ra[1]=a0.y; ra[2]=a0.z; ra[3]=a0.w;
            ra[4]=a1.x; ra[5]=a1.y; ra[6]=a1.z; ra[7]=a1.w;
            rb[0]=b0.x; rb[1]=b0.y; rb[2]=b0.z; rb[3]=b0.w;
            rb[4]=b1.x; rb[5]=b1.y; rb[6]=b1.z; rb[7]=b1.w;
#pragma unroll
            for (int i = 0; i < TM; i++)
#pragma unroll
                for (int j = 0; j < TN; j++)
                    acc[i][j] = fmaf(ra[i], rb[j], acc[i][j]);
        }
        __syncthreads();
    }

    // ---- epilogue: per-output-channel scale + bias, vectorized stores ----
    const int n0 = bn + tx * TN;
    float4 s0 = *reinterpret_cast<const float4*>(Wscale + n0);
    float4 s1 = *reinterpret_cast<const float4*>(Wscale + n0 + 4);
    float4 c0 = *reinterpret_cast<const float4*>(Bias + n0);
    float4 c1 = *reinterpret_cast<const float4*>(Bias + n0 + 4);
    float sc[TN] = {s0.x, s0.y, s0.z, s0.w, s1.x, s1.y, s1.z, s1.w};
    float bi[TN] = {c0.x, c0.y, c0.z, c0.w, c1.x, c1.y, c1.z, c1.w};

#pragma unroll
    for (int i = 0; i < TM; i++) {
        const int m = bm + ty * TM + i;
        float* orow = Out + (size_t)m * N + n0;
        float4 o0, o1;
        o0.x = fmaf(acc[i][0], sc[0], bi[0]);
        o0.y = fmaf(acc[i][1], sc[1], bi[1]);
        o0.z = fmaf(acc[i][2], sc[2], bi[2]);
        o0.w = fmaf(acc[i][3], sc[3], bi[3]);
        o1.x = fmaf(acc[i][4], sc[4], bi[4]);
        o1.y = fmaf(acc[i][5], sc[5], bi[5]);
        o1.z = fmaf(acc[i][6], sc[6], bi[6]);
        o1.w = fmaf(acc[i][7], sc[7], bi[7]);
        *reinterpret_cast<float4*>(orow)     = o0;
        *reinterpret_cast<float4*>(orow + 4) = o1;
    }
}

extern "C" void kernel_launch(void* const* d_in, const int* in_sizes, int n_in,
                              void* d_out, int out_size)
{
    const float* X      = (const float*)d_in[0];     // [M, K] fp32
    const int*   W      = (const int*)d_in[1];       // [N, K] int32 (int8 values)
    const float* Wscale = (const float*)d_in[2];     // [N] fp32
    const float* Bias   = (const float*)d_in[3];     // [N] fp32
    float*       Out    = (float*)d_out;             // [M, N] fp32

    const int N = in_sizes[2];                 // OUT (11008)
    const int K = in_sizes[1] / N;             // IN  (4096)
    const int M = in_sizes[0] / K;             // B*S (8192)

    dim3 grid(N / BN, M / BM);   // 86 x 64 (exact for this problem)
    dim3 block(256);
    int8lin_sgemm_kernel<<<grid, block>>>(X, W, Wscale, Bias, Out, M, N, K);
}

// round 4
// speedup vs baseline: 5.7238x; 5.7238x over previous
#include <cuda_runtime.h>
#include <cuda_bf16.h>
#include <stdint.h>

// Int8SymmetricLinear on sm_103 via mma.sync (HMMA bf16) — tcgen05 is
// unavailable at this harness's PTX target (sm_103 without 'a').
//
// out[M,N] = scale[n] * (X[M,K] @ W[N,K]^T) + bias[n]
// W arrives as int32 (values in [-127,127]) -> EXACT in bf16.
// X fp32 = x_hi + x_lo (two bf16 terms), fp32 accumulation:
//   acc = x_hi@W + x_lo@W   (effective K = 2*4096, rel_err ~1e-5)
//
// Prep kernels convert once into __device__ bf16 buffers; the GEMM mainloop
// is a pure cp.async + ldmatrix + mma.sync pipeline (BM=BN=128, BK=64,
// 256 thr, 2-stage double buffer, 96KB smem, 2 CTA/SM).

#define MDIM 8192
#define NDIM 11008
#define KDIM 4096

__device__ __align__(16) __nv_bfloat16 g_Xhi[(size_t)MDIM * KDIM];
__device__ __align__(16) __nv_bfloat16 g_Xlo[(size_t)MDIM * KDIM];
__device__ __align__(16) __nv_bfloat16 g_Wb [(size_t)NDIM * KDIM];

// ---------------- prep kernels ----------------

__global__ void __launch_bounds__(256)
prep_x_kernel(const float* __restrict__ X)
{
    size_t i4 = (size_t)blockIdx.x * 256 + threadIdx.x;   // unit of 4 elems
    float4 v = reinterpret_cast<const float4*>(X)[i4];
    __nv_bfloat16 h0 = __float2bfloat16_rn(v.x);
    __nv_bfloat16 h1 = __float2bfloat16_rn(v.y);
    __nv_bfloat16 h2 = __float2bfloat16_rn(v.z);
    __nv_bfloat16 h3 = __float2bfloat16_rn(v.w);
    __nv_bfloat16 l0 = __float2bfloat16_rn(v.x - __bfloat162float(h0));
    __nv_bfloat16 l1 = __float2bfloat16_rn(v.y - __bfloat162float(h1));
    __nv_bfloat16 l2 = __float2bfloat16_rn(v.z - __bfloat162float(h2));
    __nv_bfloat16 l3 = __float2bfloat16_rn(v.w - __bfloat162float(h3));
    uint2 hv, lv;
    hv.x = (uint32_t)__bfloat16_as_ushort(h0) | ((uint32_t)__bfloat16_as_ushort(h1) << 16);
    hv.y = (uint32_t)__bfloat16_as_ushort(h2) | ((uint32_t)__bfloat16_as_ushort(h3) << 16);
    lv.x = (uint32_t)__bfloat16_as_ushort(l0) | ((uint32_t)__bfloat16_as_ushort(l1) << 16);
    lv.y = (uint32_t)__bfloat16_as_ushort(l2) | ((uint32_t)__bfloat16_as_ushort(l3) << 16);
    reinterpret_cast<uint2*>(g_Xhi)[i4] = hv;
    reinterpret_cast<uint2*>(g_Xlo)[i4] = lv;
}

__global__ void __launch_bounds__(256)
prep_w_kernel(const int* __restrict__ W)
{
    size_t i4 = (size_t)blockIdx.x * 256 + threadIdx.x;
    int4 v = reinterpret_cast<const int4*>(W)[i4];
    uint2 o;
    o.x = (uint32_t)__bfloat16_as_ushort(__float2bfloat16_rn(__int2float_rn(v.x)))
        | ((uint32_t)__bfloat16_as_ushort(__float2bfloat16_rn(__int2float_rn(v.y))) << 16);
    o.y = (uint32_t)__bfloat16_as_ushort(__float2bfloat16_rn(__int2float_rn(v.z)))
        | ((uint32_t)__bfloat16_as_ushort(__float2bfloat16_rn(__int2float_rn(v.w))) << 16);
    reinterpret_cast<uint2*>(g_Wb)[i4] = o;
}

// ---------------- GEMM ----------------

#define BM 128
#define BN 128
#define BK 64                       // bf16 elems per chunk -> 128B rows
#define TILE_B (128 * 128)          // 16KB: 128 rows x 128B
#define OFF_AHI 0
#define OFF_ALO TILE_B
#define OFF_B   (2 * TILE_B)
#define STAGE_B (3 * TILE_B)        // 48KB
#define SMEM_SZ (2 * STAGE_B)       // 96KB

static __device__ __forceinline__ uint32_t smem_u32(const void* p) {
    uint32_t a;
    asm("{ .reg .u64 t; cvta.to.shared.u64 t, %1; cvt.u32.u64 %0, t; }" : "=r"(a) : "l"(p));
    return a;
}

static __device__ __forceinline__ void cp16(uint32_t saddr, const void* g) {
    asm volatile("cp.async.cg.shared.global [%0], [%1], 16;" :: "r"(saddr), "l"(g));
}
static __device__ __forceinline__ void cp_commit() {
    asm volatile("cp.async.commit_group;" ::: "memory");
}
template <int N_>
static __device__ __forceinline__ void cp_wait() {
    asm volatile("cp.async.wait_group %0;" :: "n"(N_) : "memory");
}

static __device__ __forceinline__ void ldm4(uint32_t addr, uint32_t* r) {
    asm volatile("ldmatrix.sync.aligned.m8n8.x4.shared.b16 {%0,%1,%2,%3}, [%4];"
                 : "=r"(r[0]), "=r"(r[1]), "=r"(r[2]), "=r"(r[3]) : "r"(addr));
}

static __device__ __forceinline__ void mma16816(float* c, const uint32_t* a, const uint32_t* b) {
    asm volatile(
        "mma.sync.aligned.m16n8k16.row.col.f32.bf16.bf16.f32 "
        "{%0,%1,%2,%3}, {%4,%5,%6,%7}, {%8,%9}, {%0,%1,%2,%3};"
        : "+f"(c[0]), "+f"(c[1]), "+f"(c[2]), "+f"(c[3])
        : "r"(a[0]), "r"(a[1]), "r"(a[2]), "r"(a[3]), "r"(b[0]), "r"(b[1]));
}

// smem address with SW-style 8-slot XOR swizzle; row stride 128B, 16B slots
static __device__ __forceinline__ uint32_t sw_addr(uint32_t base, int row, int slot) {
    return base + row * 128 + ((slot ^ (row & 7)) << 4);
}

extern __shared__ char smem_raw[];

__global__ void __launch_bounds__(256, 2)
gemm_bf16_kernel(const float* __restrict__ Wscale,
                 const float* __restrict__ Bias,
                 float* __restrict__ Out)
{
    const int tid    = threadIdx.x;
    const int lane   = tid & 31;
    const int wid    = tid >> 5;
    const int warp_m = wid >> 1;      // 0..3 -> m offset 32*warp_m
    const int warp_n = wid & 1;       // 0..1 -> n offset 64*warp_n
    const int bm = blockIdx.y * BM;
    const int bn = blockIdx.x * BN;
    const uint32_t sb = smem_u32(smem_raw);

    // global load mapping: 1024 16B-slots per tile, 4 per thread
    const int ld_row0 = tid >> 3;         // row advances by 32 per unit step
    const int ld_slot = tid & 7;

    float acc[2][8][4];
#pragma unroll
    for (int i = 0; i < 2; i++)
#pragma unroll
        for (int j = 0; j < 8; j++)
#pragma unroll
            for (int q = 0; q < 4; q++) acc[i][j][q] = 0.0f;

    const int NCH = KDIM / BK;   // 64

    // ---- async-load one chunk into a stage ----
    auto load_chunk = [&](int c, int stg) {
        const uint32_t st = sb + stg * STAGE_B;
        const size_t kt = (size_t)c * BK;
#pragma unroll
        for (int u = 0; u < 4; u++) {
            const int row = ld_row0 + u * 32;
            const uint32_t so = (uint32_t)(row * 128 + ((ld_slot ^ (row & 7)) << 4));
            const size_t gx = (size_t)(bm + row) * KDIM + kt + ld_slot * 8;
            const size_t gw = (size_t)(bn + row) * KDIM + kt + ld_slot * 8;
            cp16(st + OFF_AHI + so, g_Xhi + gx);
            cp16(st + OFF_ALO + so, g_Xlo + gx);
            cp16(st + OFF_B   + so, g_Wb  + gw);
        }
    };

    load_chunk(0, 0); cp_commit();
    load_chunk(1, 1); cp_commit();

    for (int c = 0; c < NCH; c++) {
        const int stg = c & 1;
        cp_wait<1>();
        __syncthreads();

        const uint32_t st  = sb + stg * STAGE_B;
        const uint32_t ahi = st + OFF_AHI;
        const uint32_t alo = st + OFF_ALO;
        const uint32_t btl = st + OFF_B;

#pragma unroll
        for (int k16 = 0; k16 < 4; k16++) {
            uint32_t bf[4][4];     // 4 n16-blocks -> 8 n8 frags
#pragma unroll
            for (int nb = 0; nb < 4; nb++) {
                const int row  = warp_n * 64 + nb * 16 + ((lane & 16) >> 1) + (lane & 7);
                const int slot = 2 * k16 + ((lane >> 3) & 1);
                ldm4(sw_addr(btl, row, slot), bf[nb]);
            }
            uint32_t ah[2][4], al[2][4];
#pragma unroll
            for (int mi = 0; mi < 2; mi++) {
                const int row  = warp_m * 32 + mi * 16 + (lane & 15);
                const int slot = 2 * k16 + (lane >> 4);
                ldm4(sw_addr(ahi, row, slot), ah[mi]);
                ldm4(sw_addr(alo, row, slot), al[mi]);
            }
#pragma unroll
            for (int mi = 0; mi < 2; mi++)
#pragma unroll
                for (int nb = 0; nb < 4; nb++) {
                    mma16816(acc[mi][nb * 2 + 0], ah[mi], &bf[nb][0]);
                    mma16816(acc[mi][nb * 2 + 1], ah[mi], &bf[nb][2]);
                }
#pragma unroll
            for (int mi = 0; mi < 2; mi++)
#pragma unroll
                for (int nb = 0; nb < 4; nb++) {
                    mma16816(acc[mi][nb * 2 + 0], al[mi], &bf[nb][0]);
                    mma16816(acc[mi][nb * 2 + 1], al[mi], &bf[nb][2]);
                }
        }

        __syncthreads();
        if (c + 2 < NCH) load_chunk(c + 2, stg);
        cp_commit();
    }

    // ---- epilogue: scale + bias, float2 stores ----
    const int n_base = bn + warp_n * 64 + (lane & 3) * 2;
    float2 sc[8], bi[8];
#pragma unroll
    for (int nj = 0; nj < 8; nj++) {
        sc[nj] = *reinterpret_cast<const float2*>(Wscale + n_base + nj * 8);
        bi[nj] = *reinterpret_cast<const float2*>(Bias   + n_base + nj * 8);
    }
#pragma unroll
    for (int mi = 0; mi < 2; mi++) {
        const int m0 = bm + warp_m * 32 + mi * 16 + (lane >> 2);
#pragma unroll
        for (int nj = 0; nj < 8; nj++) {
            const int n = n_base + nj * 8;
            float2 o0, o1;
            o0.x = fmaf(acc[mi][nj][0], sc[nj].x, bi[nj].x);
            o0.y = fmaf(acc[mi][nj][1], sc[nj].y, bi[nj].y);
            o1.x = fmaf(acc[mi][nj][2], sc[nj].x, bi[nj].x);
            o1.y = fmaf(acc[mi][nj][3], sc[nj].y, bi[nj].y);
            *reinterpret_cast<float2*>(Out + (size_t)m0 * NDIM + n)       = o0;
            *reinterpret_cast<float2*>(Out + (size_t)(m0 + 8) * NDIM + n) = o1;
        }
    }
}

// ---------------- launch ----------------

extern "C" void kernel_launch(void* const* d_in, const int* in_sizes, int n_in,
                              void* d_out, int out_size)
{
    const float* X      = (const float*)d_in[0];   // [M, K] fp32
    const int*   W      = (const int*)d_in[1];     // [N, K] int32 (int8 values)
    const float* Wscale = (const float*)d_in[2];   // [N] fp32
    const float* Bias   = (const float*)d_in[3];   // [N] fp32
    float*       Out    = (float*)d_out;           // [M, N] fp32

    // prep: fp32 -> (hi, lo) bf16; int32 -> bf16
    prep_x_kernel<<<(size_t)MDIM * KDIM / (256 * 4), 256>>>(X);
    prep_w_kernel<<<(size_t)NDIM * KDIM / (256 * 4), 256>>>(W);

    static int smem_set = 0;
    if (!smem_set) {
        cudaFuncSetAttribute(gemm_bf16_kernel,
                             cudaFuncAttributeMaxDynamicSharedMemorySize, SMEM_SZ);
        smem_set = 1;
    }
    dim3 grid(NDIM / BN, MDIM / BM);   // 86 x 64
    gemm_bf16_kernel<<<grid, 256, SMEM_SZ>>>(Wscale, Bias, Out);
}